// round 6
// baseline (speedup 1.0000x reference)
#include <cuda_runtime.h>
#include <cuda_bf16.h>
#include <stdint.h>

// ---------------- Problem shape ----------------
#define BB 8
#define NN 3136
#define DD 1536
#define PP 4096
#define MM (BB*NN)          // 25088

// ---------------- Tiling (int8) ----------------
#define BM 128
#define BN 128
#define BKB 128             // k-bytes per chunk (128 int8 = one swizzled row)
#define NKC (DD/BKB)        // 12
#define NMT (MM/BM)         // 196
#define NNT (PP/BN)         // 32
#define NITEMS (NMT*NNT)    // 6272
#define GRID 296            // 2 persistent CTAs per SM
#define THREADS 256
#define NSTAGE 3

#define STAGE_BYTES (BM*BKB + BN*BKB)        // 32768
#define SMEM_BYTES (NSTAGE*STAGE_BYTES)      // 98304

#define QSCALE 24.0f
#define INV2   (2.0f/(QSCALE*QSCALE))        // 2/576

// ---------------- Scratch (device globals: allocation-free rule) ------------
__device__ int8_t g_A[(size_t)MM*DD];          // embeds s8
__device__ int8_t g_Bc[(size_t)PP*DD];         // centroids s8
__device__ float g_nA[MM];                     // ||x||^2 (fp32, exact inputs)
__device__ float g_nB[PP];                     // ||c||^2
__device__ unsigned int g_min[MM];             // running min of dist^2 (uint bits)

// ---------------------------------------------------------------------------
// Prep: fp32 -> s8 (scale 24, clamp +-127) + fp32 squared norms + g_min init.
// ---------------------------------------------------------------------------
#define PT 128
__global__ void prep_kernel(const float* __restrict__ embeds,
                            const float* __restrict__ cents,
                            float* __restrict__ out, int loss_elems) {
    int row = blockIdx.x;
    const float4* src;
    uint32_t* dst;
    float* ndst;
    if (row < MM) {
        src = (const float4*)(embeds + (size_t)row * DD);
        dst = (uint32_t*)(g_A + (size_t)row * DD);
        ndst = g_nA + row;
        if (threadIdx.x == 0) g_min[row] = 0x7F800000u;  // +inf
    } else {
        int r = row - MM;
        src = (const float4*)(cents + (size_t)r * DD);
        dst = (uint32_t*)(g_Bc + (size_t)r * DD);
        ndst = g_nB + r;
    }
    float s = 0.f;
#pragma unroll
    for (int i = 0; i < DD / 4 / PT; ++i) {
        int j = i * PT + threadIdx.x;
        float4 v = src[j];
        int q0 = __float2int_rn(fminf(fmaxf(v.x * QSCALE, -127.f), 127.f));
        int q1 = __float2int_rn(fminf(fmaxf(v.y * QSCALE, -127.f), 127.f));
        int q2 = __float2int_rn(fminf(fmaxf(v.z * QSCALE, -127.f), 127.f));
        int q3 = __float2int_rn(fminf(fmaxf(v.w * QSCALE, -127.f), 127.f));
        dst[j] = (uint32_t)(q0 & 0xff) | ((uint32_t)(q1 & 0xff) << 8) |
                 ((uint32_t)(q2 & 0xff) << 16) | ((uint32_t)(q3 & 0xff) << 24);
        s += v.x * v.x + v.y * v.y + v.z * v.z + v.w * v.w;
    }
#pragma unroll
    for (int off = 16; off; off >>= 1)
        s += __shfl_xor_sync(0xffffffffu, s, off);
    __shared__ float ws[PT / 32];
    int lane = threadIdx.x & 31, warp = threadIdx.x >> 5;
    if (lane == 0) ws[warp] = s;
    __syncthreads();
    if (threadIdx.x == 0) {
        float t = 0.f;
#pragma unroll
        for (int w = 0; w < PT / 32; ++w) t += ws[w];
        *ndst = t;
    }
    if (row == 0 && threadIdx.x < loss_elems) out[threadIdx.x] = 0.f;
}

// ---------------------------------------------------------------------------
// PTX helpers (generic ISA only)
// ---------------------------------------------------------------------------
__device__ __forceinline__ uint32_t smem_u32(const void* p) {
    return (uint32_t)__cvta_generic_to_shared(p);
}
__device__ __forceinline__ void cp16(void* s, const void* g) {
    asm volatile("cp.async.cg.shared.global [%0], [%1], 16;\n"
                 :: "r"(smem_u32(s)), "l"(g));
}
__device__ __forceinline__ void cp_commit() {
    asm volatile("cp.async.commit_group;\n");
}
template <int N>
__device__ __forceinline__ void cp_wait() {
    asm volatile("cp.async.wait_group %0;\n" :: "n"(N));
}
__device__ __forceinline__ void ldm_x4(uint32_t* r, const int8_t* p) {
    asm volatile("ldmatrix.sync.aligned.m8n8.x4.shared.b16 {%0,%1,%2,%3}, [%4];\n"
                 : "=r"(r[0]), "=r"(r[1]), "=r"(r[2]), "=r"(r[3])
                 : "r"(smem_u32(p)));
}
__device__ __forceinline__ void mma_s8(int* c, const uint32_t* a, const uint32_t* b) {
    asm volatile("mma.sync.aligned.m16n8k32.row.col.s32.s8.s8.s32 "
                 "{%0,%1,%2,%3}, {%4,%5,%6,%7}, {%8,%9}, {%0,%1,%2,%3};\n"
                 : "+r"(c[0]), "+r"(c[1]), "+r"(c[2]), "+r"(c[3])
                 : "r"(a[0]), "r"(a[1]), "r"(a[2]), "r"(a[3]),
                   "r"(b[0]), "r"(b[1]));
}
// XOR-swizzled BYTE offset for (row, 16B-chunk c8) in a [rows][128B] tile.
__device__ __forceinline__ int swz(int row, int c8) {
    return row * BKB + ((c8 ^ (row & 7)) << 4);
}

// ---------------------------------------------------------------------------
// Persistent IMMA GEMM-min, 3-stage cp.async ring.
// Item = (m-tile 128) x (n-tile 128), full K, fold min via atomicMin.
// ---------------------------------------------------------------------------
struct SmemTile { int8_t a[BM * BKB]; int8_t b[BN * BKB]; };

__device__ __forceinline__ void issue_stage(SmemTile* st, int m0, int p0, int kc,
                                            int tid) {
    const int8_t* Ag = g_A + (size_t)m0 * DD + kc * BKB;
    const int8_t* Bg = g_Bc + (size_t)p0 * DD + kc * BKB;
#pragma unroll
    for (int t = 0; t < 4; ++t) {
        int idx = tid + t * THREADS;
        int row = idx >> 3, c8 = idx & 7;
        cp16(st->a + swz(row, c8), Ag + (size_t)row * DD + c8 * 16);
        cp16(st->b + swz(row, c8), Bg + (size_t)row * DD + c8 * 16);
    }
}

__global__ __launch_bounds__(THREADS, 2)
void gemm_min_kernel() {
    extern __shared__ __align__(16) char smem_raw[];
    SmemTile* stages = (SmemTile*)smem_raw;

    const int tid = threadIdx.x;
    const int lane = tid & 31, warp = tid >> 5;
    const int wm = warp >> 1, wn = warp & 1;          // 4(M) x 2(N) warps

    const int arow  = (lane & 7) + ((lane >> 3) & 1) * 8;  // 16-row ldmatrix addr
    const int acbit = (lane >> 4) & 1;                     // second 16B k-chunk

    for (int it = blockIdx.x; it < NITEMS; it += GRID) {
        const int m0 = (it >> 5) * BM;
        const int p0 = (it & 31) * BN;

        int acc[2][8][4];
#pragma unroll
        for (int i = 0; i < 2; ++i)
#pragma unroll
            for (int j = 0; j < 8; ++j)
#pragma unroll
                for (int k = 0; k < 4; ++k) acc[i][j][k] = 0;

        // prologue: stages 0 and 1 in flight
        issue_stage(&stages[0], m0, p0, 0, tid);
        cp_commit();
        issue_stage(&stages[1], m0, p0, 1, tid);
        cp_commit();

#pragma unroll 1
        for (int kc = 0; kc < NKC; ++kc) {
            cp_wait<1>();          // stage kc arrived
            __syncthreads();
            if (kc + 2 < NKC)
                issue_stage(&stages[(kc + 2) % NSTAGE], m0, p0, kc + 2, tid);
            cp_commit();

            const SmemTile* st = &stages[kc % NSTAGE];
#pragma unroll
            for (int ks = 0; ks < 4; ++ks) {           // 4 x k=32 per chunk
                uint32_t a[2][4];
                int c8 = ks * 2 + acbit;
#pragma unroll
                for (int mt = 0; mt < 2; ++mt) {
                    int row = wm * 32 + mt * 16 + arow;
                    ldm_x4(a[mt], st->a + swz(row, c8));
                }
                uint32_t b[8][2];
#pragma unroll
                for (int tp = 0; tp < 4; ++tp) {
                    uint32_t r[4];
                    int row = wn * 64 + tp * 16 + arow;
                    ldm_x4(r, st->b + swz(row, c8));
                    b[2 * tp][0] = r[0];  b[2 * tp][1] = r[2];
                    b[2 * tp + 1][0] = r[1]; b[2 * tp + 1][1] = r[3];
                }
#pragma unroll
                for (int mt = 0; mt < 2; ++mt)
#pragma unroll
                    for (int j = 0; j < 8; ++j)
                        mma_s8(acc[mt][j], a[mt], b[j]);
            }
        }
        __syncthreads();   // all warps done with last stage before next item

        // epilogue: dist^2 part = ||c||^2 - 2*(dot/576); fold min, atomicMin
        float rmin[2][2] = {{3.4e38f, 3.4e38f}, {3.4e38f, 3.4e38f}};
#pragma unroll
        for (int j = 0; j < 8; ++j) {
            int col = p0 + wn * 64 + j * 8 + (lane & 3) * 2;
            float nc0 = g_nB[col], nc1 = g_nB[col + 1];
#pragma unroll
            for (int mt = 0; mt < 2; ++mt) {
                float v0 = fminf(nc0 - INV2 * (float)acc[mt][j][0],
                                 nc1 - INV2 * (float)acc[mt][j][1]);
                float v1 = fminf(nc0 - INV2 * (float)acc[mt][j][2],
                                 nc1 - INV2 * (float)acc[mt][j][3]);
                rmin[mt][0] = fminf(rmin[mt][0], v0);
                rmin[mt][1] = fminf(rmin[mt][1], v1);
            }
        }
#pragma unroll
        for (int mt = 0; mt < 2; ++mt)
#pragma unroll
            for (int h = 0; h < 2; ++h) {
                float v = rmin[mt][h];
                v = fminf(v, __shfl_xor_sync(0xffffffffu, v, 1));
                v = fminf(v, __shfl_xor_sync(0xffffffffu, v, 2));
                rmin[mt][h] = v;
            }
        if ((lane & 3) == 0) {
            int q = lane >> 2;
#pragma unroll
            for (int mt = 0; mt < 2; ++mt)
#pragma unroll
                for (int h = 0; h < 2; ++h) {
                    int m = m0 + wm * 32 + mt * 16 + h * 8 + q;
                    float d2 = fmaxf(g_nA[m] + rmin[mt][h], 0.f);
                    atomicMin(&g_min[m], __float_as_uint(d2));
                }
        }
    }
}

// ---------------------------------------------------------------------------
// Final: sqrt of the folded min distance^2.
// ---------------------------------------------------------------------------
__global__ void sqrt_kernel(float* __restrict__ out, int offset) {
    int m = blockIdx.x * blockDim.x + threadIdx.x;
    if (m < MM) out[offset + m] = sqrtf(__uint_as_float(g_min[m]));
}

// ---------------------------------------------------------------------------
extern "C" void kernel_launch(void* const* d_in, const int* in_sizes, int n_in,
                              void* d_out, int out_size) {
    const float* embeds = (const float*)d_in[0];
    const float* cents  = (const float*)d_in[1];
    if (n_in >= 2 && in_sizes[0] == PP * DD && in_sizes[1] == MM * DD) {
        embeds = (const float*)d_in[1];
        cents  = (const float*)d_in[0];
    }
    float* out = (float*)d_out;
    int loss_elems = out_size - MM;
    if (loss_elems < 0) loss_elems = 0;

    cudaFuncSetAttribute(gemm_min_kernel,
                         cudaFuncAttributeMaxDynamicSharedMemorySize, SMEM_BYTES);

    prep_kernel<<<MM + PP, PT>>>(embeds, cents, out, loss_elems);
    gemm_min_kernel<<<GRID, THREADS, SMEM_BYTES>>>();
    sqrt_kernel<<<(MM + 255) / 256, 256>>>(out, loss_elems);
}

// round 7
// speedup vs baseline: 2.3083x; 2.3083x over previous
#include <cuda_runtime.h>
#include <cuda_bf16.h>
#include <stdint.h>

// ---------------- Problem shape ----------------
#define BB 8
#define NN 3136
#define DD 1536
#define PP 4096
#define MM (BB*NN)          // 25088

// ---------------- Tiling ----------------
#define BM 128
#define BN 256
#define BK 64               // bf16 per k-chunk (128 B rows)
#define NKC (DD/BK)         // 24
#define NMT (MM/BM)         // 196
#define NNT (PP/BN)         // 16
#define NITEMS (NMT*NNT)    // 3136
#define GRID 148            // 1 persistent CTA per SM
#define THREADS 256
#define NSTAGE 3

#define STAGE_BYTES ((BM+BN)*BK*2)           // 49152
#define SMEM_BYTES (NSTAGE*STAGE_BYTES)      // 147456

// ---------------- Scratch (device globals: allocation-free rule) ------------
__device__ __nv_bfloat16 g_A[(size_t)MM*DD];   // embeds bf16
__device__ __nv_bfloat16 g_Bc[(size_t)PP*DD];  // centroids bf16
__device__ float g_nA[MM];                     // ||x||^2
__device__ float g_nB[PP];                     // ||c||^2
__device__ unsigned int g_min[MM];             // running min of dist^2 (uint bits)

// ---------------------------------------------------------------------------
// Prep: fp32 -> bf16 (vectorized) + fp32 squared norms + g_min init.
// ---------------------------------------------------------------------------
#define PT 128
__global__ void prep_kernel(const float* __restrict__ embeds,
                            const float* __restrict__ cents,
                            float* __restrict__ out, int loss_elems) {
    int row = blockIdx.x;
    const float4* src;
    uint2* dst;
    float* ndst;
    if (row < MM) {
        src = (const float4*)(embeds + (size_t)row * DD);
        dst = (uint2*)(g_A + (size_t)row * DD);
        ndst = g_nA + row;
        if (threadIdx.x == 0) g_min[row] = 0x7F800000u;  // +inf
    } else {
        int r = row - MM;
        src = (const float4*)(cents + (size_t)r * DD);
        dst = (uint2*)(g_Bc + (size_t)r * DD);
        ndst = g_nB + r;
    }
    float s = 0.f;
#pragma unroll
    for (int i = 0; i < DD / 4 / PT; ++i) {
        int j = i * PT + threadIdx.x;
        float4 v = src[j];
        __nv_bfloat162 lo = __floats2bfloat162_rn(v.x, v.y);
        __nv_bfloat162 hi = __floats2bfloat162_rn(v.z, v.w);
        uint2 pk;
        pk.x = *(uint32_t*)&lo;
        pk.y = *(uint32_t*)&hi;
        dst[j] = pk;
        s += v.x * v.x + v.y * v.y + v.z * v.z + v.w * v.w;
    }
#pragma unroll
    for (int off = 16; off; off >>= 1)
        s += __shfl_xor_sync(0xffffffffu, s, off);
    __shared__ float ws[PT / 32];
    int lane = threadIdx.x & 31, warp = threadIdx.x >> 5;
    if (lane == 0) ws[warp] = s;
    __syncthreads();
    if (threadIdx.x == 0) {
        float t = 0.f;
#pragma unroll
        for (int w = 0; w < PT / 32; ++w) t += ws[w];
        *ndst = t;
    }
    if (row == 0 && threadIdx.x < loss_elems) out[threadIdx.x] = 0.f;
}

// ---------------------------------------------------------------------------
// PTX helpers (generic ISA only)
// ---------------------------------------------------------------------------
__device__ __forceinline__ uint32_t smem_u32(const void* p) {
    return (uint32_t)__cvta_generic_to_shared(p);
}
__device__ __forceinline__ void cp16(void* s, const void* g) {
    asm volatile("cp.async.cg.shared.global [%0], [%1], 16;\n"
                 :: "r"(smem_u32(s)), "l"(g));
}
__device__ __forceinline__ void cp_commit() {
    asm volatile("cp.async.commit_group;\n");
}
template <int N>
__device__ __forceinline__ void cp_wait() {
    asm volatile("cp.async.wait_group %0;\n" :: "n"(N));
}
__device__ __forceinline__ void ldm_x4(uint32_t* r, const __nv_bfloat16* p) {
    asm volatile("ldmatrix.sync.aligned.m8n8.x4.shared.b16 {%0,%1,%2,%3}, [%4];\n"
                 : "=r"(r[0]), "=r"(r[1]), "=r"(r[2]), "=r"(r[3])
                 : "r"(smem_u32(p)));
}
__device__ __forceinline__ void mma_bf16(float* c, const uint32_t* a, const uint32_t* b) {
    asm volatile("mma.sync.aligned.m16n8k16.row.col.f32.bf16.bf16.f32 "
                 "{%0,%1,%2,%3}, {%4,%5,%6,%7}, {%8,%9}, {%0,%1,%2,%3};\n"
                 : "+f"(c[0]), "+f"(c[1]), "+f"(c[2]), "+f"(c[3])
                 : "r"(a[0]), "r"(a[1]), "r"(a[2]), "r"(a[3]),
                   "r"(b[0]), "r"(b[1]));
}
// XOR-swizzled half offset for (row, 16B-chunk c8) in a [rows][64]-half tile.
__device__ __forceinline__ int swz(int row, int c8) {
    return row * 64 + ((c8 ^ (row & 7)) << 3);
}

// ---------------------------------------------------------------------------
// Persistent HMMA GEMM-min, 128x256 CTA tile, 64x64 warp tiles (2x4 grid).
// ---------------------------------------------------------------------------
struct SmemTile { __nv_bfloat16 a[BM * 64]; __nv_bfloat16 b[BN * 64]; };

__device__ __forceinline__ void issue_stage(SmemTile* st, int m0, int p0, int kc,
                                            int tid) {
    const __nv_bfloat16* Ag = g_A + (size_t)m0 * DD + kc * BK;
    const __nv_bfloat16* Bg = g_Bc + (size_t)p0 * DD + kc * BK;
    // A: 1024 16B-chunks (4 iters); B: 2048 (8 iters)
#pragma unroll
    for (int t = 0; t < 4; ++t) {
        int idx = tid + t * THREADS;
        int row = idx >> 3, c8 = idx & 7;
        cp16(st->a + swz(row, c8), Ag + (size_t)row * DD + c8 * 8);
    }
#pragma unroll
    for (int t = 0; t < 8; ++t) {
        int idx = tid + t * THREADS;
        int row = idx >> 3, c8 = idx & 7;
        cp16(st->b + swz(row, c8), Bg + (size_t)row * DD + c8 * 8);
    }
}

__global__ __launch_bounds__(THREADS, 1)
void gemm_min_kernel() {
    extern __shared__ __align__(16) char smem_raw[];
    SmemTile* stages = (SmemTile*)smem_raw;

    const int tid = threadIdx.x;
    const int lane = tid & 31, warp = tid >> 5;
    const int wm = warp >> 2, wn = warp & 3;          // 2(M) x 4(N) warps

    const int arow  = (lane & 7) + ((lane >> 3) & 1) * 8;
    const int acbit = (lane >> 4) & 1;

    for (int it = blockIdx.x; it < NITEMS; it += GRID) {
        const int m0 = (it >> 4) * BM;        // 196 m-tiles
        const int p0 = (it & 15) * BN;        // 16 n-tiles

        float acc[4][8][4];                   // [mt 4x16 rows][j 8x8 cols][frag]
#pragma unroll
        for (int i = 0; i < 4; ++i)
#pragma unroll
            for (int j = 0; j < 8; ++j)
#pragma unroll
                for (int k = 0; k < 4; ++k) acc[i][j][k] = 0.f;

        issue_stage(&stages[0], m0, p0, 0, tid);
        cp_commit();
        issue_stage(&stages[1], m0, p0, 1, tid);
        cp_commit();

#pragma unroll 1
        for (int kc = 0; kc < NKC; ++kc) {
            cp_wait<1>();
            __syncthreads();
            if (kc + 2 < NKC)
                issue_stage(&stages[(kc + 2) % NSTAGE], m0, p0, kc + 2, tid);
            cp_commit();

            const SmemTile* st = &stages[kc % NSTAGE];
#pragma unroll
            for (int ks = 0; ks < BK / 16; ++ks) {
                int c8 = ks * 2 + acbit;
                uint32_t a[4][4];
#pragma unroll
                for (int mt = 0; mt < 4; ++mt) {
                    int row = wm * 64 + mt * 16 + arow;
                    ldm_x4(a[mt], st->a + swz(row, c8));
                }
                uint32_t b[8][2];
#pragma unroll
                for (int tp = 0; tp < 4; ++tp) {
                    uint32_t r[4];
                    int row = wn * 64 + tp * 16 + arow;
                    ldm_x4(r, st->b + swz(row, c8));
                    b[2 * tp][0] = r[0];  b[2 * tp][1] = r[2];
                    b[2 * tp + 1][0] = r[1]; b[2 * tp + 1][1] = r[3];
                }
#pragma unroll
                for (int mt = 0; mt < 4; ++mt)
#pragma unroll
                    for (int j = 0; j < 8; ++j)
                        mma_bf16(acc[mt][j], a[mt], b[j]);
            }
        }
        __syncthreads();   // last stage consumed by all before next item

        // epilogue: min over this warp's 64 cols, fold, atomicMin
        float rmin[4][2];
#pragma unroll
        for (int mt = 0; mt < 4; ++mt) { rmin[mt][0] = 3.4e38f; rmin[mt][1] = 3.4e38f; }
#pragma unroll
        for (int j = 0; j < 8; ++j) {
            int col = p0 + wn * 64 + j * 8 + (lane & 3) * 2;
            float nc0 = g_nB[col], nc1 = g_nB[col + 1];
#pragma unroll
            for (int mt = 0; mt < 4; ++mt) {
                float v0 = fminf(nc0 - 2.f * acc[mt][j][0],
                                 nc1 - 2.f * acc[mt][j][1]);
                float v1 = fminf(nc0 - 2.f * acc[mt][j][2],
                                 nc1 - 2.f * acc[mt][j][3]);
                rmin[mt][0] = fminf(rmin[mt][0], v0);
                rmin[mt][1] = fminf(rmin[mt][1], v1);
            }
        }
#pragma unroll
        for (int mt = 0; mt < 4; ++mt)
#pragma unroll
            for (int h = 0; h < 2; ++h) {
                float v = rmin[mt][h];
                v = fminf(v, __shfl_xor_sync(0xffffffffu, v, 1));
                v = fminf(v, __shfl_xor_sync(0xffffffffu, v, 2));
                rmin[mt][h] = v;
            }
        if ((lane & 3) == 0) {
            int q = lane >> 2;
#pragma unroll
            for (int mt = 0; mt < 4; ++mt)
#pragma unroll
                for (int h = 0; h < 2; ++h) {
                    int m = m0 + wm * 64 + mt * 16 + h * 8 + q;
                    float d2 = fmaxf(g_nA[m] + rmin[mt][h], 0.f);
                    atomicMin(&g_min[m], __float_as_uint(d2));
                }
        }
    }
}

// ---------------------------------------------------------------------------
// Final: sqrt of the folded min distance^2.
// ---------------------------------------------------------------------------
__global__ void sqrt_kernel(float* __restrict__ out, int offset) {
    int m = blockIdx.x * blockDim.x + threadIdx.x;
    if (m < MM) out[offset + m] = sqrtf(__uint_as_float(g_min[m]));
}

// ---------------------------------------------------------------------------
extern "C" void kernel_launch(void* const* d_in, const int* in_sizes, int n_in,
                              void* d_out, int out_size) {
    const float* embeds = (const float*)d_in[0];
    const float* cents  = (const float*)d_in[1];
    if (n_in >= 2 && in_sizes[0] == PP * DD && in_sizes[1] == MM * DD) {
        embeds = (const float*)d_in[1];
        cents  = (const float*)d_in[0];
    }
    float* out = (float*)d_out;
    int loss_elems = out_size - MM;
    if (loss_elems < 0) loss_elems = 0;

    cudaFuncSetAttribute(gemm_min_kernel,
                         cudaFuncAttributeMaxDynamicSharedMemorySize, SMEM_BYTES);

    prep_kernel<<<MM + PP, PT>>>(embeds, cents, out, loss_elems);
    gemm_min_kernel<<<GRID, THREADS, SMEM_BYTES>>>();
    sqrt_kernel<<<(MM + 255) / 256, 256>>>(out, loss_elems);
}

// round 8
// speedup vs baseline: 2.6342x; 1.1412x over previous
#include <cuda_runtime.h>
#include <cuda_fp16.h>
#include <stdint.h>

// ---------------- Problem shape ----------------
#define BB 8
#define NN 3136
#define DD 1536
#define PP 4096
#define MM (BB*NN)          // 25088

// ---------------- Tiling ----------------
#define BM 128
#define BN 128
#define BK 64               // fp16 per k-chunk (128 B rows)
#define NKC (DD/BK)         // 24
#define NMT (MM/BM)         // 196
#define NNT (PP/BN)         // 32
#define NITEMS (NMT*NNT)    // 6272
#define GRID 296            // 2 persistent CTAs per SM
#define THREADS 256

#define SMEM_BYTES (2*BM*64*2 + 2*BN*64*2)   // 65536 (double-buffered A+B)

// ---------------- Scratch (device globals: allocation-free rule) ------------
__device__ __half g_A[(size_t)MM*DD];          // embeds f16
__device__ __half g_Bc[(size_t)PP*DD];         // centroids f16
__device__ float g_nA[MM];                     // ||x||^2 (fp32 from fp32 inputs)
__device__ float g_nB[PP];                     // ||c||^2
__device__ unsigned int g_min[MM];             // running min of dist^2 (uint bits)

// ---------------------------------------------------------------------------
// Prep: fp32 -> fp16 (vectorized) + fp32 squared norms + g_min init.
// ---------------------------------------------------------------------------
#define PT 128
__global__ void prep_kernel(const float* __restrict__ embeds,
                            const float* __restrict__ cents,
                            float* __restrict__ out, int loss_elems) {
    int row = blockIdx.x;
    const float4* src;
    uint2* dst;
    float* ndst;
    if (row < MM) {
        src = (const float4*)(embeds + (size_t)row * DD);
        dst = (uint2*)(g_A + (size_t)row * DD);
        ndst = g_nA + row;
        if (threadIdx.x == 0) g_min[row] = 0x7F800000u;  // +inf
    } else {
        int r = row - MM;
        src = (const float4*)(cents + (size_t)r * DD);
        dst = (uint2*)(g_Bc + (size_t)r * DD);
        ndst = g_nB + r;
    }
    float s = 0.f;
#pragma unroll
    for (int i = 0; i < DD / 4 / PT; ++i) {
        int j = i * PT + threadIdx.x;
        float4 v = src[j];
        __half2 lo = __floats2half2_rn(v.x, v.y);
        __half2 hi = __floats2half2_rn(v.z, v.w);
        uint2 pk;
        pk.x = *(uint32_t*)&lo;
        pk.y = *(uint32_t*)&hi;
        dst[j] = pk;
        s += v.x * v.x + v.y * v.y + v.z * v.z + v.w * v.w;
    }
#pragma unroll
    for (int off = 16; off; off >>= 1)
        s += __shfl_xor_sync(0xffffffffu, s, off);
    __shared__ float ws[PT / 32];
    int lane = threadIdx.x & 31, warp = threadIdx.x >> 5;
    if (lane == 0) ws[warp] = s;
    __syncthreads();
    if (threadIdx.x == 0) {
        float t = 0.f;
#pragma unroll
        for (int w = 0; w < PT / 32; ++w) t += ws[w];
        *ndst = t;
    }
    if (row == 0 && threadIdx.x < loss_elems) out[threadIdx.x] = 0.f;
}

// ---------------------------------------------------------------------------
// PTX helpers (generic ISA only)
// ---------------------------------------------------------------------------
__device__ __forceinline__ uint32_t smem_u32(const void* p) {
    return (uint32_t)__cvta_generic_to_shared(p);
}
__device__ __forceinline__ void cp16(void* s, const void* g) {
    asm volatile("cp.async.cg.shared.global [%0], [%1], 16;\n"
                 :: "r"(smem_u32(s)), "l"(g));
}
__device__ __forceinline__ void cp_commit() {
    asm volatile("cp.async.commit_group;\n");
}
template <int N>
__device__ __forceinline__ void cp_wait() {
    asm volatile("cp.async.wait_group %0;\n" :: "n"(N));
}
__device__ __forceinline__ void ldm_x4(uint32_t* r, const __half* p) {
    asm volatile("ldmatrix.sync.aligned.m8n8.x4.shared.b16 {%0,%1,%2,%3}, [%4];\n"
                 : "=r"(r[0]), "=r"(r[1]), "=r"(r[2]), "=r"(r[3])
                 : "r"(smem_u32(p)));
}
// fp16 inputs, fp16 accumulators: potentially 2x HMMA rate
__device__ __forceinline__ void mma_f16(uint32_t* c, const uint32_t* a,
                                        const uint32_t* b) {
    asm volatile("mma.sync.aligned.m16n8k16.row.col.f16.f16.f16.f16 "
                 "{%0,%1}, {%2,%3,%4,%5}, {%6,%7}, {%0,%1};\n"
                 : "+r"(c[0]), "+r"(c[1])
                 : "r"(a[0]), "r"(a[1]), "r"(a[2]), "r"(a[3]),
                   "r"(b[0]), "r"(b[1]));
}
// XOR-swizzled half offset for (row, 16B-chunk c8) in a [rows][64]-half tile.
__device__ __forceinline__ int swz(int row, int c8) {
    return row * 64 + ((c8 ^ (row & 7)) << 3);
}

// ---------------------------------------------------------------------------
// Persistent HMMA(f16-acc) GEMM-min. 296 CTAs, 2/SM, 6272 items.
// Item = (m-tile 128) x (n-tile 128), full K, fold min via atomicMin.
// ---------------------------------------------------------------------------
__global__ __launch_bounds__(THREADS, 2)
void gemm_min_kernel() {
    extern __shared__ __align__(16) char smem_raw[];
    __half* As = (__half*)smem_raw;                   // 2 x [128][64]
    __half* Bs = As + 2 * BM * 64;                    // 2 x [128][64]

    const int tid = threadIdx.x;
    const int lane = tid & 31, warp = tid >> 5;
    const int wm = warp >> 1, wn = warp & 1;          // 4(M) x 2(N) warps

    const int arow  = (lane & 7) + ((lane >> 3) & 1) * 8;
    const int acbit = (lane >> 4) & 1;

    for (int it = blockIdx.x; it < NITEMS; it += GRID) {
        const int m0 = (it >> 5) * BM;
        const int p0 = (it & 31) * BN;

        uint32_t acc[2][8][2];                        // f16x2 accumulators
#pragma unroll
        for (int i = 0; i < 2; ++i)
#pragma unroll
            for (int j = 0; j < 8; ++j) { acc[i][j][0] = 0u; acc[i][j][1] = 0u; }

        // prologue: chunk 0 -> buffer 0
        {
            const __half* Ag = g_A + (size_t)m0 * DD;
            const __half* Bg = g_Bc + (size_t)p0 * DD;
#pragma unroll
            for (int t = 0; t < 4; ++t) {
                int idx = tid + t * THREADS;
                int row = idx >> 3, c8 = idx & 7;
                cp16(As + swz(row, c8), Ag + (size_t)row * DD + c8 * 8);
                cp16(Bs + swz(row, c8), Bg + (size_t)row * DD + c8 * 8);
            }
            cp_commit();
        }

#pragma unroll 1
        for (int kc = 0; kc < NKC; ++kc) {
            if (kc + 1 < NKC) {
                int buf = (kc + 1) & 1;
                const __half* Ag = g_A + (size_t)m0 * DD + (kc + 1) * BK;
                const __half* Bg = g_Bc + (size_t)p0 * DD + (kc + 1) * BK;
                __half* Asb = As + buf * BM * 64;
                __half* Bsb = Bs + buf * BN * 64;
#pragma unroll
                for (int t = 0; t < 4; ++t) {
                    int idx = tid + t * THREADS;
                    int row = idx >> 3, c8 = idx & 7;
                    cp16(Asb + swz(row, c8), Ag + (size_t)row * DD + c8 * 8);
                    cp16(Bsb + swz(row, c8), Bg + (size_t)row * DD + c8 * 8);
                }
                cp_commit();
                cp_wait<1>();
            } else {
                cp_wait<0>();
            }
            __syncthreads();

            const __half* Asb = As + (kc & 1) * BM * 64;
            const __half* Bsb = Bs + (kc & 1) * BN * 64;
#pragma unroll
            for (int ks = 0; ks < BK / 16; ++ks) {
                uint32_t a[2][4];
                int c8 = ks * 2 + acbit;
#pragma unroll
                for (int mt = 0; mt < 2; ++mt) {
                    int row = wm * 32 + mt * 16 + arow;
                    ldm_x4(a[mt], Asb + swz(row, c8));
                }
                uint32_t b[8][2];
#pragma unroll
                for (int tp = 0; tp < 4; ++tp) {
                    uint32_t r[4];
                    int row = wn * 64 + tp * 16 + arow;
                    ldm_x4(r, Bsb + swz(row, c8));
                    b[2 * tp][0] = r[0];  b[2 * tp][1] = r[2];
                    b[2 * tp + 1][0] = r[1]; b[2 * tp + 1][1] = r[3];
                }
#pragma unroll
                for (int mt = 0; mt < 2; ++mt)
#pragma unroll
                    for (int j = 0; j < 8; ++j)
                        mma_f16(acc[mt][j], a[mt], b[j]);
            }
            __syncthreads();
        }

        // epilogue: unpack f16x2 accs, min over warp's 64 cols, atomicMin
        float rmin[2][2] = {{3.4e38f, 3.4e38f}, {3.4e38f, 3.4e38f}};
#pragma unroll
        for (int j = 0; j < 8; ++j) {
            int col = p0 + wn * 64 + j * 8 + (lane & 3) * 2;
            float nc0 = g_nB[col], nc1 = g_nB[col + 1];
#pragma unroll
            for (int mt = 0; mt < 2; ++mt) {
                float2 lo = __half22float2(*(__half2*)&acc[mt][j][0]); // row r
                float2 hi = __half22float2(*(__half2*)&acc[mt][j][1]); // row r+8
                float v0 = fminf(nc0 - 2.f * lo.x, nc1 - 2.f * lo.y);
                float v1 = fminf(nc0 - 2.f * hi.x, nc1 - 2.f * hi.y);
                rmin[mt][0] = fminf(rmin[mt][0], v0);
                rmin[mt][1] = fminf(rmin[mt][1], v1);
            }
        }
#pragma unroll
        for (int mt = 0; mt < 2; ++mt)
#pragma unroll
            for (int h = 0; h < 2; ++h) {
                float v = rmin[mt][h];
                v = fminf(v, __shfl_xor_sync(0xffffffffu, v, 1));
                v = fminf(v, __shfl_xor_sync(0xffffffffu, v, 2));
                rmin[mt][h] = v;
            }
        if ((lane & 3) == 0) {
            int q = lane >> 2;
#pragma unroll
            for (int mt = 0; mt < 2; ++mt)
#pragma unroll
                for (int h = 0; h < 2; ++h) {
                    int m = m0 + wm * 32 + mt * 16 + h * 8 + q;
                    float d2 = fmaxf(g_nA[m] + rmin[mt][h], 0.f);
                    atomicMin(&g_min[m], __float_as_uint(d2));
                }
        }
    }
}

// ---------------------------------------------------------------------------
// Final: sqrt of the folded min distance^2.
// ---------------------------------------------------------------------------
__global__ void sqrt_kernel(float* __restrict__ out, int offset) {
    int m = blockIdx.x * blockDim.x + threadIdx.x;
    if (m < MM) out[offset + m] = sqrtf(__uint_as_float(g_min[m]));
}

// ---------------------------------------------------------------------------
extern "C" void kernel_launch(void* const* d_in, const int* in_sizes, int n_in,
                              void* d_out, int out_size) {
    const float* embeds = (const float*)d_in[0];
    const float* cents  = (const float*)d_in[1];
    if (n_in >= 2 && in_sizes[0] == PP * DD && in_sizes[1] == MM * DD) {
        embeds = (const float*)d_in[1];
        cents  = (const float*)d_in[0];
    }
    float* out = (float*)d_out;
    int loss_elems = out_size - MM;
    if (loss_elems < 0) loss_elems = 0;

    cudaFuncSetAttribute(gemm_min_kernel,
                         cudaFuncAttributeMaxDynamicSharedMemorySize, SMEM_BYTES);

    prep_kernel<<<MM + PP, PT>>>(embeds, cents, out, loss_elems);
    gemm_min_kernel<<<GRID, THREADS, SMEM_BYTES>>>();
    sqrt_kernel<<<(MM + 255) / 256, 256>>>(out, loss_elems);
}